// round 14
// baseline (speedup 1.0000x reference)
#include <cuda_runtime.h>
#include <cuda_bf16.h>
#include <cuda_fp16.h>
#include <cstdint>
#include <math.h>

#define EMB   512
#define NHEAD 8
#define DHEAD 64
#define SEQ   2048
#define BATCH 4
#define MROWS (BATCH*SEQ)

// Scratch (no cudaMalloc allowed)
__device__ __nv_bfloat16 g_ah[3*MROWS*EMB], g_al[3*MROWS*EMB];   // split inputs (q,k,v)
__device__ __nv_bfloat16 g_wh[4*EMB*EMB], g_wl[4*EMB*EMB];       // split weights
__device__ __nv_bfloat16 g_q[MROWS*EMB], g_k[MROWS*EMB];         // quantized ints (bf16 exact)
__device__ __half        g_vh[MROWS*EMB];                        // quantized v (f16 exact)
__device__ __nv_bfloat16 g_oh[MROWS*EMB], g_ol[MROWS*EMB];       // attn out, pre-split

// ---------------------------------------------------------------------------
// helpers
// ---------------------------------------------------------------------------
__device__ __forceinline__ uint32_t pk_bf16x2(float lo, float hi) {
    uint32_t r;
    asm("cvt.rn.bf16x2.f32 %0, %1, %2;" : "=r"(r) : "f"(hi), "f"(lo));
    return r;
}
__device__ __forceinline__ uint32_t pk_f16x2(float lo, float hi) {
    uint32_t r;
    asm("cvt.rn.f16x2.f32 %0, %1, %2;" : "=r"(r) : "f"(hi), "f"(lo));
    return r;
}
__device__ __forceinline__ void split2(float a, float b, uint32_t& hi, uint32_t& lo) {
    uint32_t ha = __float_as_uint(a) & 0xFFFF0000u;
    uint32_t hb = __float_as_uint(b) & 0xFFFF0000u;
    hi = hb | (ha >> 16);
    lo = pk_bf16x2(a - __uint_as_float(ha), b - __uint_as_float(hb));
}
__device__ __forceinline__ void mma16816(float* c, const uint32_t* a, uint32_t b0, uint32_t b1) {
    asm volatile(
        "mma.sync.aligned.m16n8k16.row.col.f32.bf16.bf16.f32 "
        "{%0,%1,%2,%3}, {%4,%5,%6,%7}, {%8,%9}, {%0,%1,%2,%3};"
        : "+f"(c[0]), "+f"(c[1]), "+f"(c[2]), "+f"(c[3])
        : "r"(a[0]), "r"(a[1]), "r"(a[2]), "r"(a[3]), "r"(b0), "r"(b1));
}
__device__ __forceinline__ void mma16816h(float* c, const uint32_t* a, uint32_t b0, uint32_t b1) {
    asm volatile(
        "mma.sync.aligned.m16n8k16.row.col.f32.f16.f16.f32 "
        "{%0,%1,%2,%3}, {%4,%5,%6,%7}, {%8,%9}, {%0,%1,%2,%3};"
        : "+f"(c[0]), "+f"(c[1]), "+f"(c[2]), "+f"(c[3])
        : "r"(a[0]), "r"(a[1]), "r"(a[2]), "r"(a[3]), "r"(b0), "r"(b1));
}
__device__ __forceinline__ void ldm4(uint32_t& r0, uint32_t& r1, uint32_t& r2, uint32_t& r3, uint32_t a) {
    asm volatile("ldmatrix.sync.aligned.m8n8.x4.shared.b16 {%0,%1,%2,%3}, [%4];"
        : "=r"(r0), "=r"(r1), "=r"(r2), "=r"(r3) : "r"(a));
}
__device__ __forceinline__ void ldm4t(uint32_t& r0, uint32_t& r1, uint32_t& r2, uint32_t& r3, uint32_t a) {
    asm volatile("ldmatrix.sync.aligned.m8n8.x4.trans.shared.b16 {%0,%1,%2,%3}, [%4];"
        : "=r"(r0), "=r"(r1), "=r"(r2), "=r"(r3) : "r"(a));
}
// L1-bypass fill: data is consumed from SMEM via ldmatrix, never re-read via L1.
__device__ __forceinline__ void cp16(uint32_t dst, const void* src) {
    asm volatile("cp.async.cg.shared.global [%0], [%1], 16;" :: "r"(dst), "l"(src));
}
__device__ __forceinline__ uint32_t smem_u32(const void* p) {
    uint32_t a;
    asm("{ .reg .u64 t; cvta.to.shared.u64 t, %1; cvt.u32.u64 %0, t; }" : "=r"(a) : "l"(p));
    return a;
}
__device__ __forceinline__ float mexp2(float x) {
    float r;
    asm("ex2.approx.f32 %0, %1;" : "=f"(r) : "f"(x));
    return r;
}

// ---------------------------------------------------------------------------
// multi-source split fp32 -> (hi, lo) bf16; blockIdx.y selects job
// ---------------------------------------------------------------------------
struct SplitJob { const float4* in; uint2* hi; uint2* lo; int n4; };

__global__ __launch_bounds__(256) void split_multi(
    SplitJob j0, SplitJob j1, SplitJob j2, SplitJob j3)
{
    SplitJob j = (blockIdx.y == 0) ? j0 : (blockIdx.y == 1) ? j1
               : (blockIdx.y == 2) ? j2 : j3;
    for (int i = blockIdx.x * 256 + threadIdx.x; i < j.n4; i += gridDim.x * 256) {
        float4 v = j.in[i];
        uint32_t h0, l0, h1, l1;
        split2(v.x, v.y, h0, l0);
        split2(v.z, v.w, h1, l1);
        j.hi[i] = make_uint2(h0, h1);
        j.lo[i] = make_uint2(l0, l1);
    }
}

// ---------------------------------------------------------------------------
// bf16 pre-split GEMM (single-barrier pipeline):
// CTA tile 128x128, BK=32, 2-stage cp.async, warp tile 32x64.
// 256 thr / 8 warps (4m x 2n). 80B smem rows.
// Stage layout (bytes): Ah@0  Al@10240  Wh@20480  Wl@30720. Stage=40960.
// omode: 0 = fp32 out, 1 = bf16 quant ints, 2 = f16 quant values.
// ---------------------------------------------------------------------------
#define GSTAGE 40960
#define GEMM_SMEM (2*GSTAGE)

struct GemmJob {
    const __nv_bfloat16 *agh, *agl, *wgh, *wgl;
    const float* bias;
    void* out;
    int omode;
};

__device__ __forceinline__ void gemm_core(
    const GemmJob& J, const float* bqp, const float* eqp, char* smptr)
{
    const uint32_t smb = smem_u32(smptr);
    const int tid = threadIdx.x, wid = tid >> 5, lane = tid & 31;
    const int g = lane >> 2, tig = lane & 3, mat = lane >> 3, lrow = lane & 7;
    const int m0 = blockIdx.y * 128, n0 = blockIdx.x * 128;
    const int mw = (wid & 3) * 32, nw = (wid >> 2) * 64;

    const uint32_t aoff = (uint32_t)((((mat & 1) * 8 + lrow) * 80) + (mat >> 1) * 16);
    const uint32_t boff = (uint32_t)((((mat >> 1) * 8 + lrow) * 80) + (mat & 1) * 16);

    const int sr = tid >> 1;
    const int sc = (tid & 1) * 16;

    float o[2][8][4] = {};

    const __nv_bfloat16* a0p = J.agh + (size_t)(m0 + sr) * EMB + sc;
    const __nv_bfloat16* a1p = J.agl + (size_t)(m0 + sr) * EMB + sc;
    const __nv_bfloat16* w0p = J.wgh + (size_t)(n0 + sr) * EMB + sc;
    const __nv_bfloat16* w1p = J.wgl + (size_t)(n0 + sr) * EMB + sc;
    const uint32_t ds = (uint32_t)(sr * 80 + sc * 2);

    #define GEMM_ISSUE(s, kb) do { \
        uint32_t base = smb + (uint32_t)(s) * GSTAGE; \
        cp16(base + ds,          a0p + (kb));  cp16(base + ds + 16,          a0p + (kb) + 8); \
        cp16(base + ds + 10240u, a1p + (kb));  cp16(base + ds + 10240u + 16, a1p + (kb) + 8); \
        cp16(base + ds + 20480u, w0p + (kb));  cp16(base + ds + 20480u + 16, w0p + (kb) + 8); \
        cp16(base + ds + 30720u, w1p + (kb));  cp16(base + ds + 30720u + 16, w1p + (kb) + 8); \
        asm volatile("cp.async.commit_group;" ::: "memory"); \
    } while (0)

    GEMM_ISSUE(0, 0);

    for (int it = 0; it < 16; it++) {
        const int buf = it & 1;
        asm volatile("cp.async.wait_group 0;" ::: "memory");
        __syncthreads();
        // issue AFTER the barrier: the buffer being filled (buf^1) was consumed
        // at iter it-1 and the barrier proves all warps are done with it.
        if (it + 1 < 16) GEMM_ISSUE(buf ^ 1, (it + 1) * 32);

        const uint32_t base = smb + (uint32_t)buf * GSTAGE;
        #pragma unroll
        for (int u = 0; u < 2; u++) {
            const uint32_t ka = base + (uint32_t)(mw * 80) + aoff + u * 32;
            uint32_t AH0[4], AH1[4], AL0[4], AL1[4];
            ldm4(AH0[0], AH0[1], AH0[2], AH0[3], ka);
            ldm4(AH1[0], AH1[1], AH1[2], AH1[3], ka + 1280u);
            ldm4(AL0[0], AL0[1], AL0[2], AL0[3], ka + 10240u);
            ldm4(AL1[0], AL1[1], AL1[2], AL1[3], ka + 10240u + 1280u);
            #pragma unroll
            for (int jp = 0; jp < 4; jp++) {
                const uint32_t kb = base + 20480u + (uint32_t)((nw + jp*16) * 80) + boff + u * 32;
                uint32_t bh[4], bl[4];
                ldm4(bh[0], bh[1], bh[2], bh[3], kb);
                ldm4(bl[0], bl[1], bl[2], bl[3], kb + 10240u);
                mma16816(o[0][2*jp],   AH0, bh[0], bh[1]);
                mma16816(o[0][2*jp],   AL0, bh[0], bh[1]);
                mma16816(o[0][2*jp],   AH0, bl[0], bl[1]);
                mma16816(o[1][2*jp],   AH1, bh[0], bh[1]);
                mma16816(o[1][2*jp],   AL1, bh[0], bh[1]);
                mma16816(o[1][2*jp],   AH1, bl[0], bl[1]);
                mma16816(o[0][2*jp+1], AH0, bh[2], bh[3]);
                mma16816(o[0][2*jp+1], AL0, bh[2], bh[3]);
                mma16816(o[0][2*jp+1], AH0, bl[2], bl[3]);
                mma16816(o[1][2*jp+1], AH1, bh[2], bh[3]);
                mma16816(o[1][2*jp+1], AL1, bh[2], bh[3]);
                mma16816(o[1][2*jp+1], AH1, bl[2], bl[3]);
            }
        }
    }

    const int omode = J.omode;
    float qs = 1.f, qinv = 1.f, qlo = 0.f, qhi = 0.f;
    if (omode != 0) {
        float b = fminf(fmaxf(*bqp, 1.0f), 8.0f);
        float e = *eqp;
        qs = exp2f(e); qinv = exp2f(-e);
        float p = exp2f(b - 1.0f);
        qlo = -p; qhi = p - 1.0f;
    }
    #pragma unroll
    for (int mt = 0; mt < 2; mt++) {
        #pragma unroll
        for (int j = 0; j < 8; j++) {
            int r0 = m0 + mw + mt*16 + g;
            int nn = n0 + nw + j*8 + tig*2;
            float b0 = J.bias[nn], b1 = J.bias[nn+1];
            float r[4] = { o[mt][j][0]+b0, o[mt][j][1]+b1, o[mt][j][2]+b0, o[mt][j][3]+b1 };
            if (omode != 0) {
                #pragma unroll
                for (int q = 0; q < 4; q++) {
                    float t = r[q] * qinv;
                    r[q] = floorf(fminf(fmaxf(t, qlo), qhi)) * qs;
                }
            }
            if (omode == 1) {
                __nv_bfloat16* C = (__nv_bfloat16*)J.out;
                *(uint32_t*)&C[(size_t)r0 * EMB + nn]     = pk_bf16x2(r[0], r[1]);
                *(uint32_t*)&C[(size_t)(r0+8) * EMB + nn] = pk_bf16x2(r[2], r[3]);
            } else if (omode == 2) {
                __half* C = (__half*)J.out;
                *(uint32_t*)&C[(size_t)r0 * EMB + nn]     = pk_f16x2(r[0], r[1]);
                *(uint32_t*)&C[(size_t)(r0+8) * EMB + nn] = pk_f16x2(r[2], r[3]);
            } else {
                float* C = (float*)J.out;
                *(float2*)&C[(size_t)r0 * EMB + nn]     = make_float2(r[0], r[1]);
                *(float2*)&C[(size_t)(r0+8) * EMB + nn] = make_float2(r[2], r[3]);
            }
        }
    }
}

__global__ __launch_bounds__(256, 2) void gemm_fused3(
    GemmJob j0, GemmJob j1, GemmJob j2,
    const float* __restrict__ bqp, const float* __restrict__ eqp)
{
    extern __shared__ __align__(16) char sm[];
    const GemmJob& J = (blockIdx.z == 0) ? j0 : (blockIdx.z == 1) ? j1 : j2;
    gemm_core(J, bqp, eqp, sm);
}

__global__ __launch_bounds__(256, 2) void gemm_single(
    GemmJob j0, const float* __restrict__ bqp, const float* __restrict__ eqp)
{
    extern __shared__ __align__(16) char sm[];
    gemm_core(j0, bqp, eqp, sm);
}

// ---------------------------------------------------------------------------
// Flash attention (R9 config): 128 thr / 4 warps, BQ=64, BK=64.
// bf16 S (exact), fp16 single-product PV, MUFU exp, hysteresis max,
// cp.async double-buffer, ldmatrix fragments.
// ---------------------------------------------------------------------------
#define KSTR 72
#define TILEB (64*KSTR)
#define MARG 15.0f

__global__ __launch_bounds__(128, 4) void flash_hmma(
    const __nv_bfloat16* __restrict__ gq, const __nv_bfloat16* __restrict__ gk,
    const __half* __restrict__ gv,
    __nv_bfloat16* __restrict__ goh, __nv_bfloat16* __restrict__ gol)
{
    __shared__ __align__(16) __nv_bfloat16 Kb[2][TILEB];
    __shared__ __align__(16) __half        Vb[2][TILEB];

    const int tid  = threadIdx.x;
    const int wid  = tid >> 5;
    const int lane = tid & 31;
    const int g    = lane >> 2;
    const int tig  = lane & 3;
    const int mat  = lane >> 3;
    const int lrow = lane & 7;

    const int q0 = blockIdx.x * 64;
    const int h  = blockIdx.y;
    const int n  = blockIdx.z;

    const __nv_bfloat16* qb  = gq + ((size_t)n*SEQ + q0 + wid*16)*EMB + h*DHEAD;
    const __nv_bfloat16* kb0 = gk + (size_t)n*SEQ*EMB + h*DHEAD;
    const __half*        vb0 = gv + (size_t)n*SEQ*EMB + h*DHEAD;

    const uint32_t kbase[2] = { smem_u32(&Kb[0][0]), smem_u32(&Kb[1][0]) };
    const uint32_t vbase[2] = { smem_u32(&Vb[0][0]), smem_u32(&Vb[1][0]) };

    const uint32_t koff = (uint32_t)(((mat>>1)*8 + lrow) * 144 + (mat&1)*16);
    const uint32_t voff = (uint32_t)(((mat&1)*8 + lrow) * 144 + (mat>>1)*16);

    const int srow = tid >> 3;
    const int sseg = tid & 7;

    uint32_t qa[4][4];
    {
        const __nv_bfloat16* r0 = qb + (size_t)g*EMB;
        const __nv_bfloat16* r1 = qb + (size_t)(g+8)*EMB;
        #pragma unroll
        for (int u = 0; u < 4; u++) {
            int d0 = tig*2 + 16*u;
            qa[u][0] = *(const uint32_t*)(r0 + d0);
            qa[u][1] = *(const uint32_t*)(r1 + d0);
            qa[u][2] = *(const uint32_t*)(r0 + d0 + 8);
            qa[u][3] = *(const uint32_t*)(r1 + d0 + 8);
        }
    }

    float o[8][4];
    #pragma unroll
    for (int j = 0; j < 8; j++) { o[j][0]=0.f; o[j][1]=0.f; o[j][2]=0.f; o[j][3]=0.f; }
    float m0 = 0.f, m1 = 0.f, l0 = 0.f, l1 = 0.f;

    const float C = 0.06375892f;

    {
        #pragma unroll
        for (int i = 0; i < 4; i++) {
            int row = srow + i*16;
            uint32_t d = (uint32_t)(row*144 + sseg*16);
            cp16(kbase[0] + d, kb0 + (size_t)row*EMB + sseg*8);
            cp16(vbase[0] + d, vb0 + (size_t)row*EMB + sseg*8);
        }
        asm volatile("cp.async.commit_group;" ::: "memory");
    }

    for (int t = 0; t < SEQ/64; t++) {
        const int buf = t & 1;
        if (t + 1 < SEQ/64) {
            const __nv_bfloat16* kb = kb0 + (size_t)((t+1)*64)*EMB;
            const __half*        vb = vb0 + (size_t)((t+1)*64)*EMB;
            const int nb = buf ^ 1;
            #pragma unroll
            for (int i = 0; i < 4; i++) {
                int row = srow + i*16;
                uint32_t d = (uint32_t)(row*144 + sseg*16);
                cp16(kbase[nb] + d, kb + (size_t)row*EMB + sseg*8);
                cp16(vbase[nb] + d, vb + (size_t)row*EMB + sseg*8);
            }
            asm volatile("cp.async.commit_group;" ::: "memory");
            asm volatile("cp.async.wait_group 1;" ::: "memory");
        } else {
            asm volatile("cp.async.wait_group 0;" ::: "memory");
        }
        __syncthreads();

        const uint32_t kK = kbase[buf] + koff;
        const uint32_t kV = vbase[buf] + voff;

        float sacc[8][4];
        #pragma unroll
        for (int j = 0; j < 8; j++) { sacc[j][0]=0.f; sacc[j][1]=0.f; sacc[j][2]=0.f; sacc[j][3]=0.f; }
        #pragma unroll
        for (int u = 0; u < 4; u++) {
            #pragma unroll
            for (int jp = 0; jp < 4; jp++) {
                uint32_t b00, b01, b10, b11;
                ldm4(b00, b01, b10, b11, kK + jp*2304u + u*32u);
                mma16816(sacc[2*jp],   qa[u], b00, b01);
                mma16816(sacc[2*jp+1], qa[u], b10, b11);
            }
        }

        float rm0 = fmaxf(sacc[0][0], sacc[0][1]), rm1 = fmaxf(sacc[0][2], sacc[0][3]);
        #pragma unroll
        for (int j = 1; j < 8; j++) {
            rm0 = fmaxf(rm0, fmaxf(sacc[j][0], sacc[j][1]));
            rm1 = fmaxf(rm1, fmaxf(sacc[j][2], sacc[j][3]));
        }
        rm0 = fmaxf(rm0, __shfl_xor_sync(0xffffffffu, rm0, 1));
        rm0 = fmaxf(rm0, __shfl_xor_sync(0xffffffffu, rm0, 2));
        rm1 = fmaxf(rm1, __shfl_xor_sync(0xffffffffu, rm1, 1));
        rm1 = fmaxf(rm1, __shfl_xor_sync(0xffffffffu, rm1, 2));

        if (t == 0) {
            m0 = rm0 + MARG;
            m1 = rm1 + MARG;
        } else if (rm0 > m0 || rm1 > m1) {
            float a0 = 1.0f, a1 = 1.0f;
            if (rm0 > m0) { float nm = rm0 + MARG; a0 = mexp2((m0 - nm) * C); m0 = nm; }
            if (rm1 > m1) { float nm = rm1 + MARG; a1 = mexp2((m1 - nm) * C); m1 = nm; }
            l0 *= a0;  l1 *= a1;
            #pragma unroll
            for (int j = 0; j < 8; j++) {
                o[j][0] *= a0; o[j][1] *= a0; o[j][2] *= a1; o[j][3] *= a1;
            }
        }
        float mc0 = m0 * C, mc1 = m1 * C;

        uint32_t phA[8], phB[8];
        #pragma unroll
        for (int j = 0; j < 8; j++) {
            float p0 = mexp2(fmaf(sacc[j][0], C, -mc0));
            float p1 = mexp2(fmaf(sacc[j][1], C, -mc0));
            float p2 = mexp2(fmaf(sacc[j][2], C, -mc1));
            float p3 = mexp2(fmaf(sacc[j][3], C, -mc1));
            l0 += p0 + p1;  l1 += p2 + p3;
            phA[j] = pk_f16x2(p0, p1);
            phB[j] = pk_f16x2(p2, p3);
        }

        #pragma unroll
        for (int u = 0; u < 4; u++) {
            uint32_t ah[4] = { phA[2*u], phB[2*u], phA[2*u+1], phB[2*u+1] };
            #pragma unroll
            for (int jp = 0; jp < 4; jp++) {
                uint32_t c00, c01, c10, c11;
                ldm4t(c00, c01, c10, c11, kV + u*2304u + jp*32u);
                mma16816h(o[2*jp],   ah, c00, c01);
                mma16816h(o[2*jp+1], ah, c10, c11);
            }
        }
        __syncthreads();
    }

    l0 += __shfl_xor_sync(0xffffffffu, l0, 1);
    l0 += __shfl_xor_sync(0xffffffffu, l0, 2);
    l1 += __shfl_xor_sync(0xffffffffu, l1, 1);
    l1 += __shfl_xor_sync(0xffffffffu, l1, 2);
    float i0 = 1.0f / l0, i1 = 1.0f / l1;

    const size_t ob = ((size_t)n*SEQ + q0 + wid*16)*EMB + h*DHEAD;
    #pragma unroll
    for (int j = 0; j < 8; j++) {
        int nn = 8*j + tig*2;
        uint32_t h0, l0u, h1, l1u;
        split2(o[j][0]*i0, o[j][1]*i0, h0, l0u);
        split2(o[j][2]*i1, o[j][3]*i1, h1, l1u);
        *(uint32_t*)&goh[ob + (size_t)g*EMB + nn]     = h0;
        *(uint32_t*)&gol[ob + (size_t)g*EMB + nn]     = l0u;
        *(uint32_t*)&goh[ob + (size_t)(g+8)*EMB + nn] = h1;
        *(uint32_t*)&gol[ob + (size_t)(g+8)*EMB + nn] = l1u;
    }
}

// ---------------------------------------------------------------------------
extern "C" void kernel_launch(void* const* d_in, const int* in_sizes, int n_in,
                              void* d_out, int out_size)
{
    const float* values = (const float*)d_in[0];
    const float* keys   = (const float*)d_in[1];
    const float* query  = (const float*)d_in[2];
    const float* Wq = (const float*)d_in[3];  const float* bq = (const float*)d_in[4];
    const float* Wk = (const float*)d_in[5];  const float* bk = (const float*)d_in[6];
    const float* Wv = (const float*)d_in[7];  const float* bv = (const float*)d_in[8];
    const float* Wo = (const float*)d_in[9];  const float* bo = (const float*)d_in[10];
    const float* bpar = (const float*)d_in[11];
    const float* epar = (const float*)d_in[12];

    __nv_bfloat16 *ah, *al, *wh, *wl, *pq, *pk, *oh, *ol;
    __half *pvh;
    cudaGetSymbolAddress((void**)&ah, g_ah);
    cudaGetSymbolAddress((void**)&al, g_al);
    cudaGetSymbolAddress((void**)&wh, g_wh);
    cudaGetSymbolAddress((void**)&wl, g_wl);
    cudaGetSymbolAddress((void**)&pq, g_q);
    cudaGetSymbolAddress((void**)&pk, g_k);
    cudaGetSymbolAddress((void**)&pvh, g_vh);
    cudaGetSymbolAddress((void**)&oh, g_oh);
    cudaGetSymbolAddress((void**)&ol, g_ol);

    const int N4  = MROWS*EMB/4;
    const int NW4 = EMB*EMB/4;
    const size_t IN = (size_t)MROWS*EMB;
    const size_t WN = (size_t)EMB*EMB;

    cudaFuncSetAttribute(gemm_fused3, cudaFuncAttributeMaxDynamicSharedMemorySize, GEMM_SMEM);
    cudaFuncSetAttribute(gemm_single, cudaFuncAttributeMaxDynamicSharedMemorySize, GEMM_SMEM);

    {
        SplitJob jw0 = { (const float4*)Wq, (uint2*)(wh + 0*WN), (uint2*)(wl + 0*WN), NW4 };
        SplitJob jw1 = { (const float4*)Wk, (uint2*)(wh + 1*WN), (uint2*)(wl + 1*WN), NW4 };
        SplitJob jw2 = { (const float4*)Wv, (uint2*)(wh + 2*WN), (uint2*)(wl + 2*WN), NW4 };
        SplitJob jw3 = { (const float4*)Wo, (uint2*)(wh + 3*WN), (uint2*)(wl + 3*WN), NW4 };
        split_multi<<<dim3(NW4/256, 4), 256>>>(jw0, jw1, jw2, jw3);
    }
    {
        SplitJob ji0 = { (const float4*)query,  (uint2*)(ah + 0*IN), (uint2*)(al + 0*IN), N4 };
        SplitJob ji1 = { (const float4*)keys,   (uint2*)(ah + 1*IN), (uint2*)(al + 1*IN), N4 };
        SplitJob ji2 = { (const float4*)values, (uint2*)(ah + 2*IN), (uint2*)(al + 2*IN), N4 };
        SplitJob ji3 = { (const float4*)query,  (uint2*)(ah + 0*IN), (uint2*)(al + 0*IN), 0 };
        split_multi<<<dim3(1024, 3), 256>>>(ji0, ji1, ji2, ji3);
    }

    // fused q/k/v projection GEMMs
    {
        GemmJob j0 = { ah + 0*IN, al + 0*IN, wh + 0*WN, wl + 0*WN, bq, pq,  1 };
        GemmJob j1 = { ah + 1*IN, al + 1*IN, wh + 1*WN, wl + 1*WN, bk, pk,  1 };
        GemmJob j2 = { ah + 2*IN, al + 2*IN, wh + 2*WN, wl + 2*WN, bv, pvh, 2 };
        gemm_fused3<<<dim3(EMB/128, MROWS/128, 3), 256, GEMM_SMEM>>>(j0, j1, j2, bpar, epar);
    }

    flash_hmma<<<dim3(SEQ/64, NHEAD, BATCH), 128>>>(pq, pk, pvh, oh, ol);

    {
        GemmJob jo = { oh, ol, wh + 3*WN, wl + 3*WN, bo, (float*)d_out, 0 };
        gemm_single<<<dim3(EMB/128, MROWS/128), 256, GEMM_SMEM>>>(jo, bpar, epar);
    }
}

// round 15
// speedup vs baseline: 1.0330x; 1.0330x over previous
#include <cuda_runtime.h>
#include <cuda_bf16.h>
#include <cuda_fp16.h>
#include <cstdint>
#include <math.h>

#define EMB   512
#define NHEAD 8
#define DHEAD 64
#define SEQ   2048
#define BATCH 4
#define MROWS (BATCH*SEQ)

// Scratch (no cudaMalloc allowed)
__device__ __nv_bfloat16 g_ah[3*MROWS*EMB], g_al[3*MROWS*EMB];   // split inputs (q,k,v)
__device__ __nv_bfloat16 g_wh[4*EMB*EMB], g_wl[4*EMB*EMB];       // split weights
__device__ __nv_bfloat16 g_q[MROWS*EMB], g_k[MROWS*EMB];         // quantized ints (bf16 exact)
__device__ __half        g_vh[MROWS*EMB];                        // quantized v (f16 exact)
__device__ __nv_bfloat16 g_oh[MROWS*EMB], g_ol[MROWS*EMB];       // attn out, pre-split

// ---------------------------------------------------------------------------
// helpers
// ---------------------------------------------------------------------------
__device__ __forceinline__ uint32_t pk_bf16x2(float lo, float hi) {
    uint32_t r;
    asm("cvt.rn.bf16x2.f32 %0, %1, %2;" : "=r"(r) : "f"(hi), "f"(lo));
    return r;
}
__device__ __forceinline__ uint32_t pk_f16x2(float lo, float hi) {
    uint32_t r;
    asm("cvt.rn.f16x2.f32 %0, %1, %2;" : "=r"(r) : "f"(hi), "f"(lo));
    return r;
}
__device__ __forceinline__ void split2(float a, float b, uint32_t& hi, uint32_t& lo) {
    uint32_t ha = __float_as_uint(a) & 0xFFFF0000u;
    uint32_t hb = __float_as_uint(b) & 0xFFFF0000u;
    hi = hb | (ha >> 16);
    lo = pk_bf16x2(a - __uint_as_float(ha), b - __uint_as_float(hb));
}
__device__ __forceinline__ void mma16816(float* c, const uint32_t* a, uint32_t b0, uint32_t b1) {
    asm volatile(
        "mma.sync.aligned.m16n8k16.row.col.f32.bf16.bf16.f32 "
        "{%0,%1,%2,%3}, {%4,%5,%6,%7}, {%8,%9}, {%0,%1,%2,%3};"
        : "+f"(c[0]), "+f"(c[1]), "+f"(c[2]), "+f"(c[3])
        : "r"(a[0]), "r"(a[1]), "r"(a[2]), "r"(a[3]), "r"(b0), "r"(b1));
}
__device__ __forceinline__ void mma16816h(float* c, const uint32_t* a, uint32_t b0, uint32_t b1) {
    asm volatile(
        "mma.sync.aligned.m16n8k16.row.col.f32.f16.f16.f32 "
        "{%0,%1,%2,%3}, {%4,%5,%6,%7}, {%8,%9}, {%0,%1,%2,%3};"
        : "+f"(c[0]), "+f"(c[1]), "+f"(c[2]), "+f"(c[3])
        : "r"(a[0]), "r"(a[1]), "r"(a[2]), "r"(a[3]), "r"(b0), "r"(b1));
}
__device__ __forceinline__ void ldm4(uint32_t& r0, uint32_t& r1, uint32_t& r2, uint32_t& r3, uint32_t a) {
    asm volatile("ldmatrix.sync.aligned.m8n8.x4.shared.b16 {%0,%1,%2,%3}, [%4];"
        : "=r"(r0), "=r"(r1), "=r"(r2), "=r"(r3) : "r"(a));
}
__device__ __forceinline__ void ldm4t(uint32_t& r0, uint32_t& r1, uint32_t& r2, uint32_t& r3, uint32_t a) {
    asm volatile("ldmatrix.sync.aligned.m8n8.x4.trans.shared.b16 {%0,%1,%2,%3}, [%4];"
        : "=r"(r0), "=r"(r1), "=r"(r2), "=r"(r3) : "r"(a));
}
// GEMM staging: .ca (weight tiles re-read by co-resident/successive CTAs -> L1 reuse)
__device__ __forceinline__ void cp16ca(uint32_t dst, const void* src) {
    asm volatile("cp.async.ca.shared.global [%0], [%1], 16;" :: "r"(dst), "l"(src));
}
// Flash staging: .cg (K/V tiles are streaming, single-consumer -> bypass L1)
__device__ __forceinline__ void cp16cg(uint32_t dst, const void* src) {
    asm volatile("cp.async.cg.shared.global [%0], [%1], 16;" :: "r"(dst), "l"(src));
}
__device__ __forceinline__ uint32_t smem_u32(const void* p) {
    uint32_t a;
    asm("{ .reg .u64 t; cvta.to.shared.u64 t, %1; cvt.u32.u64 %0, t; }" : "=r"(a) : "l"(p));
    return a;
}
__device__ __forceinline__ float mexp2(float x) {
    float r;
    asm("ex2.approx.f32 %0, %1;" : "=f"(r) : "f"(x));
    return r;
}

// ---------------------------------------------------------------------------
// multi-source split fp32 -> (hi, lo) bf16; blockIdx.y selects job
// ---------------------------------------------------------------------------
struct SplitJob { const float4* in; uint2* hi; uint2* lo; int n4; };

__global__ __launch_bounds__(256) void split_multi(
    SplitJob j0, SplitJob j1, SplitJob j2, SplitJob j3)
{
    SplitJob j = (blockIdx.y == 0) ? j0 : (blockIdx.y == 1) ? j1
               : (blockIdx.y == 2) ? j2 : j3;
    for (int i = blockIdx.x * 256 + threadIdx.x; i < j.n4; i += gridDim.x * 256) {
        float4 v = j.in[i];
        uint32_t h0, l0, h1, l1;
        split2(v.x, v.y, h0, l0);
        split2(v.z, v.w, h1, l1);
        j.hi[i] = make_uint2(h0, h1);
        j.lo[i] = make_uint2(l0, l1);
    }
}

// ---------------------------------------------------------------------------
// bf16 pre-split GEMM (single-barrier pipeline):
// CTA tile 128x128, BK=32, 2-stage cp.async, warp tile 32x64.
// 256 thr / 8 warps (4m x 2n). 80B smem rows.
// Stage layout (bytes): Ah@0  Al@10240  Wh@20480  Wl@30720. Stage=40960.
// omode: 0 = fp32 out, 1 = bf16 quant ints, 2 = f16 quant values.
// ---------------------------------------------------------------------------
#define GSTAGE 40960
#define GEMM_SMEM (2*GSTAGE)

struct GemmJob {
    const __nv_bfloat16 *agh, *agl, *wgh, *wgl;
    const float* bias;
    void* out;
    int omode;
};

__device__ __forceinline__ void gemm_core(
    const GemmJob& J, const float* bqp, const float* eqp, char* smptr)
{
    const uint32_t smb = smem_u32(smptr);
    const int tid = threadIdx.x, wid = tid >> 5, lane = tid & 31;
    const int g = lane >> 2, tig = lane & 3, mat = lane >> 3, lrow = lane & 7;
    const int m0 = blockIdx.y * 128, n0 = blockIdx.x * 128;
    const int mw = (wid & 3) * 32, nw = (wid >> 2) * 64;

    const uint32_t aoff = (uint32_t)((((mat & 1) * 8 + lrow) * 80) + (mat >> 1) * 16);
    const uint32_t boff = (uint32_t)((((mat >> 1) * 8 + lrow) * 80) + (mat & 1) * 16);

    const int sr = tid >> 1;
    const int sc = (tid & 1) * 16;

    float o[2][8][4] = {};

    const __nv_bfloat16* a0p = J.agh + (size_t)(m0 + sr) * EMB + sc;
    const __nv_bfloat16* a1p = J.agl + (size_t)(m0 + sr) * EMB + sc;
    const __nv_bfloat16* w0p = J.wgh + (size_t)(n0 + sr) * EMB + sc;
    const __nv_bfloat16* w1p = J.wgl + (size_t)(n0 + sr) * EMB + sc;
    const uint32_t ds = (uint32_t)(sr * 80 + sc * 2);

    #define GEMM_ISSUE(s, kb) do { \
        uint32_t base = smb + (uint32_t)(s) * GSTAGE; \
        cp16ca(base + ds,          a0p + (kb));  cp16ca(base + ds + 16,          a0p + (kb) + 8); \
        cp16ca(base + ds + 10240u, a1p + (kb));  cp16ca(base + ds + 10240u + 16, a1p + (kb) + 8); \
        cp16ca(base + ds + 20480u, w0p + (kb));  cp16ca(base + ds + 20480u + 16, w0p + (kb) + 8); \
        cp16ca(base + ds + 30720u, w1p + (kb));  cp16ca(base + ds + 30720u + 16, w1p + (kb) + 8); \
        asm volatile("cp.async.commit_group;" ::: "memory"); \
    } while (0)

    GEMM_ISSUE(0, 0);

    for (int it = 0; it < 16; it++) {
        const int buf = it & 1;
        asm volatile("cp.async.wait_group 0;" ::: "memory");
        __syncthreads();
        // issue AFTER the barrier: the buffer being filled (buf^1) was consumed
        // at iter it-1 and the barrier proves all warps are done with it.
        if (it + 1 < 16) GEMM_ISSUE(buf ^ 1, (it + 1) * 32);

        const uint32_t base = smb + (uint32_t)buf * GSTAGE;
        #pragma unroll
        for (int u = 0; u < 2; u++) {
            const uint32_t ka = base + (uint32_t)(mw * 80) + aoff + u * 32;
            uint32_t AH0[4], AH1[4], AL0[4], AL1[4];
            ldm4(AH0[0], AH0[1], AH0[2], AH0[3], ka);
            ldm4(AH1[0], AH1[1], AH1[2], AH1[3], ka + 1280u);
            ldm4(AL0[0], AL0[1], AL0[2], AL0[3], ka + 10240u);
            ldm4(AL1[0], AL1[1], AL1[2], AL1[3], ka + 10240u + 1280u);
            #pragma unroll
            for (int jp = 0; jp < 4; jp++) {
                const uint32_t kb = base + 20480u + (uint32_t)((nw + jp*16) * 80) + boff + u * 32;
                uint32_t bh[4], bl[4];
                ldm4(bh[0], bh[1], bh[2], bh[3], kb);
                ldm4(bl[0], bl[1], bl[2], bl[3], kb + 10240u);
                mma16816(o[0][2*jp],   AH0, bh[0], bh[1]);
                mma16816(o[0][2*jp],   AL0, bh[0], bh[1]);
                mma16816(o[0][2*jp],   AH0, bl[0], bl[1]);
                mma16816(o[1][2*jp],   AH1, bh[0], bh[1]);
                mma16816(o[1][2*jp],   AL1, bh[0], bh[1]);
                mma16816(o[1][2*jp],   AH1, bl[0], bl[1]);
                mma16816(o[0][2*jp+1], AH0, bh[2], bh[3]);
                mma16816(o[0][2*jp+1], AL0, bh[2], bh[3]);
                mma16816(o[0][2*jp+1], AH0, bl[2], bl[3]);
                mma16816(o[1][2*jp+1], AH1, bh[2], bh[3]);
                mma16816(o[1][2*jp+1], AL1, bh[2], bh[3]);
                mma16816(o[1][2*jp+1], AH1, bl[2], bl[3]);
            }
        }
    }

    const int omode = J.omode;
    float qs = 1.f, qinv = 1.f, qlo = 0.f, qhi = 0.f;
    if (omode != 0) {
        float b = fminf(fmaxf(*bqp, 1.0f), 8.0f);
        float e = *eqp;
        qs = exp2f(e); qinv = exp2f(-e);
        float p = exp2f(b - 1.0f);
        qlo = -p; qhi = p - 1.0f;
    }
    #pragma unroll
    for (int mt = 0; mt < 2; mt++) {
        #pragma unroll
        for (int j = 0; j < 8; j++) {
            int r0 = m0 + mw + mt*16 + g;
            int nn = n0 + nw + j*8 + tig*2;
            float b0 = J.bias[nn], b1 = J.bias[nn+1];
            float r[4] = { o[mt][j][0]+b0, o[mt][j][1]+b1, o[mt][j][2]+b0, o[mt][j][3]+b1 };
            if (omode != 0) {
                #pragma unroll
                for (int q = 0; q < 4; q++) {
                    float t = r[q] * qinv;
                    r[q] = floorf(fminf(fmaxf(t, qlo), qhi)) * qs;
                }
            }
            if (omode == 1) {
                __nv_bfloat16* C = (__nv_bfloat16*)J.out;
                *(uint32_t*)&C[(size_t)r0 * EMB + nn]     = pk_bf16x2(r[0], r[1]);
                *(uint32_t*)&C[(size_t)(r0+8) * EMB + nn] = pk_bf16x2(r[2], r[3]);
            } else if (omode == 2) {
                __half* C = (__half*)J.out;
                *(uint32_t*)&C[(size_t)r0 * EMB + nn]     = pk_f16x2(r[0], r[1]);
                *(uint32_t*)&C[(size_t)(r0+8) * EMB + nn] = pk_f16x2(r[2], r[3]);
            } else {
                float* C = (float*)J.out;
                *(float2*)&C[(size_t)r0 * EMB + nn]     = make_float2(r[0], r[1]);
                *(float2*)&C[(size_t)(r0+8) * EMB + nn] = make_float2(r[2], r[3]);
            }
        }
    }
}

__global__ __launch_bounds__(256, 2) void gemm_fused3(
    GemmJob j0, GemmJob j1, GemmJob j2,
    const float* __restrict__ bqp, const float* __restrict__ eqp)
{
    extern __shared__ __align__(16) char sm[];
    const GemmJob& J = (blockIdx.z == 0) ? j0 : (blockIdx.z == 1) ? j1 : j2;
    gemm_core(J, bqp, eqp, sm);
}

__global__ __launch_bounds__(256, 2) void gemm_single(
    GemmJob j0, const float* __restrict__ bqp, const float* __restrict__ eqp)
{
    extern __shared__ __align__(16) char sm[];
    gemm_core(j0, bqp, eqp, sm);
}

// ---------------------------------------------------------------------------
// Flash attention (R9 config): 128 thr / 4 warps, BQ=64, BK=64.
// bf16 S (exact), fp16 single-product PV, MUFU exp, hysteresis max,
// cp.async.cg double-buffer, ldmatrix fragments.
// ---------------------------------------------------------------------------
#define KSTR 72
#define TILEB (64*KSTR)
#define MARG 15.0f

__global__ __launch_bounds__(128, 4) void flash_hmma(
    const __nv_bfloat16* __restrict__ gq, const __nv_bfloat16* __restrict__ gk,
    const __half* __restrict__ gv,
    __nv_bfloat16* __restrict__ goh, __nv_bfloat16* __restrict__ gol)
{
    __shared__ __align__(16) __nv_bfloat16 Kb[2][TILEB];
    __shared__ __align__(16) __half        Vb[2][TILEB];

    const int tid  = threadIdx.x;
    const int wid  = tid >> 5;
    const int lane = tid & 31;
    const int g    = lane >> 2;
    const int tig  = lane & 3;
    const int mat  = lane >> 3;
    const int lrow = lane & 7;

    const int q0 = blockIdx.x * 64;
    const int h  = blockIdx.y;
    const int n  = blockIdx.z;

    const __nv_bfloat16* qb  = gq + ((size_t)n*SEQ + q0 + wid*16)*EMB + h*DHEAD;
    const __nv_bfloat16* kb0 = gk + (size_t)n*SEQ*EMB + h*DHEAD;
    const __half*        vb0 = gv + (size_t)n*SEQ*EMB + h*DHEAD;

    const uint32_t kbase[2] = { smem_u32(&Kb[0][0]), smem_u32(&Kb[1][0]) };
    const uint32_t vbase[2] = { smem_u32(&Vb[0][0]), smem_u32(&Vb[1][0]) };

    const uint32_t koff = (uint32_t)(((mat>>1)*8 + lrow) * 144 + (mat&1)*16);
    const uint32_t voff = (uint32_t)(((mat&1)*8 + lrow) * 144 + (mat>>1)*16);

    const int srow = tid >> 3;
    const int sseg = tid & 7;

    uint32_t qa[4][4];
    {
        const __nv_bfloat16* r0 = qb + (size_t)g*EMB;
        const __nv_bfloat16* r1 = qb + (size_t)(g+8)*EMB;
        #pragma unroll
        for (int u = 0; u < 4; u++) {
            int d0 = tig*2 + 16*u;
            qa[u][0] = *(const uint32_t*)(r0 + d0);
            qa[u][1] = *(const uint32_t*)(r1 + d0);
            qa[u][2] = *(const uint32_t*)(r0 + d0 + 8);
            qa[u][3] = *(const uint32_t*)(r1 + d0 + 8);
        }
    }

    float o[8][4];
    #pragma unroll
    for (int j = 0; j < 8; j++) { o[j][0]=0.f; o[j][1]=0.f; o[j][2]=0.f; o[j][3]=0.f; }
    float m0 = 0.f, m1 = 0.f, l0 = 0.f, l1 = 0.f;

    const float C = 0.06375892f;

    {
        #pragma unroll
        for (int i = 0; i < 4; i++) {
            int row = srow + i*16;
            uint32_t d = (uint32_t)(row*144 + sseg*16);
            cp16cg(kbase[0] + d, kb0 + (size_t)row*EMB + sseg*8);
            cp16cg(vbase[0] + d, vb0 + (size_t)row*EMB + sseg*8);
        }
        asm volatile("cp.async.commit_group;" ::: "memory");
    }

    for (int t = 0; t < SEQ/64; t++) {
        const int buf = t & 1;
        if (t + 1 < SEQ/64) {
            const __nv_bfloat16* kb = kb0 + (size_t)((t+1)*64)*EMB;
            const __half*        vb = vb0 + (size_t)((t+1)*64)*EMB;
            const int nb = buf ^ 1;
            #pragma unroll
            for (int i = 0; i < 4; i++) {
                int row = srow + i*16;
                uint32_t d = (uint32_t)(row*144 + sseg*16);
                cp16cg(kbase[nb] + d, kb + (size_t)row*EMB + sseg*8);
                cp16cg(vbase[nb] + d, vb + (size_t)row*EMB + sseg*8);
            }
            asm volatile("cp.async.commit_group;" ::: "memory");
            asm volatile("cp.async.wait_group 1;" ::: "memory");
        } else {
            asm volatile("cp.async.wait_group 0;" ::: "memory");
        }
        __syncthreads();

        const uint32_t kK = kbase[buf] + koff;
        const uint32_t kV = vbase[buf] + voff;

        float sacc[8][4];
        #pragma unroll
        for (int j = 0; j < 8; j++) { sacc[j][0]=0.f; sacc[j][1]=0.f; sacc[j][2]=0.f; sacc[j][3]=0.f; }
        #pragma unroll
        for (int u = 0; u < 4; u++) {
            #pragma unroll
            for (int jp = 0; jp < 4; jp++) {
                uint32_t b00, b01, b10, b11;
                ldm4(b00, b01, b10, b11, kK + jp*2304u + u*32u);
                mma16816(sacc[2*jp],   qa[u], b00, b01);
                mma16816(sacc[2*jp+1], qa[u], b10, b11);
            }
        }

        float rm0 = fmaxf(sacc[0][0], sacc[0][1]), rm1 = fmaxf(sacc[0][2], sacc[0][3]);
        #pragma unroll
        for (int j = 1; j < 8; j++) {
            rm0 = fmaxf(rm0, fmaxf(sacc[j][0], sacc[j][1]));
            rm1 = fmaxf(rm1, fmaxf(sacc[j][2], sacc[j][3]));
        }
        rm0 = fmaxf(rm0, __shfl_xor_sync(0xffffffffu, rm0, 1));
        rm0 = fmaxf(rm0, __shfl_xor_sync(0xffffffffu, rm0, 2));
        rm1 = fmaxf(rm1, __shfl_xor_sync(0xffffffffu, rm1, 1));
        rm1 = fmaxf(rm1, __shfl_xor_sync(0xffffffffu, rm1, 2));

        if (t == 0) {
            m0 = rm0 + MARG;
            m1 = rm1 + MARG;
        } else if (rm0 > m0 || rm1 > m1) {
            float a0 = 1.0f, a1 = 1.0f;
            if (rm0 > m0) { float nm = rm0 + MARG; a0 = mexp2((m0 - nm) * C); m0 = nm; }
            if (rm1 > m1) { float nm = rm1 + MARG; a1 = mexp2((m1 - nm) * C); m1 = nm; }
            l0 *= a0;  l1 *= a1;
            #pragma unroll
            for (int j = 0; j < 8; j++) {
                o[j][0] *= a0; o[j][1] *= a0; o[j][2] *= a1; o[j][3] *= a1;
            }
        }
        float mc0 = m0 * C, mc1 = m1 * C;

        uint32_t phA[8], phB[8];
        #pragma unroll
        for (int j = 0; j < 8; j++) {
            float p0 = mexp2(fmaf(sacc[j][0], C, -mc0));
            float p1 = mexp2(fmaf(sacc[j][1], C, -mc0));
            float p2 = mexp2(fmaf(sacc[j][2], C, -mc1));
            float p3 = mexp2(fmaf(sacc[j][3], C, -mc1));
            l0 += p0 + p1;  l1 += p2 + p3;
            phA[j] = pk_f16x2(p0, p1);
            phB[j] = pk_f16x2(p2, p3);
        }

        #pragma unroll
        for (int u = 0; u < 4; u++) {
            uint32_t ah[4] = { phA[2*u], phB[2*u], phA[2*u+1], phB[2*u+1] };
            #pragma unroll
            for (int jp = 0; jp < 4; jp++) {
                uint32_t c00, c01, c10, c11;
                ldm4t(c00, c01, c10, c11, kV + u*2304u + jp*32u);
                mma16816h(o[2*jp],   ah, c00, c01);
                mma16816h(o[2*jp+1], ah, c10, c11);
            }
        }
        __syncthreads();
    }

    l0 += __shfl_xor_sync(0xffffffffu, l0, 1);
    l0 += __shfl_xor_sync(0xffffffffu, l0, 2);
    l1 += __shfl_xor_sync(0xffffffffu, l1, 1);
    l1 += __shfl_xor_sync(0xffffffffu, l1, 2);
    float i0 = 1.0f / l0, i1 = 1.0f / l1;

    const size_t ob = ((size_t)n*SEQ + q0 + wid*16)*EMB + h*DHEAD;
    #pragma unroll
    for (int j = 0; j < 8; j++) {
        int nn = 8*j + tig*2;
        uint32_t h0, l0u, h1, l1u;
        split2(o[j][0]*i0, o[j][1]*i0, h0, l0u);
        split2(o[j][2]*i1, o[j][3]*i1, h1, l1u);
        *(uint32_t*)&goh[ob + (size_t)g*EMB + nn]     = h0;
        *(uint32_t*)&gol[ob + (size_t)g*EMB + nn]     = l0u;
        *(uint32_t*)&goh[ob + (size_t)(g+8)*EMB + nn] = h1;
        *(uint32_t*)&gol[ob + (size_t)(g+8)*EMB + nn] = l1u;
    }
}

// ---------------------------------------------------------------------------
extern "C" void kernel_launch(void* const* d_in, const int* in_sizes, int n_in,
                              void* d_out, int out_size)
{
    const float* values = (const float*)d_in[0];
    const float* keys   = (const float*)d_in[1];
    const float* query  = (const float*)d_in[2];
    const float* Wq = (const float*)d_in[3];  const float* bq = (const float*)d_in[4];
    const float* Wk = (const float*)d_in[5];  const float* bk = (const float*)d_in[6];
    const float* Wv = (const float*)d_in[7];  const float* bv = (const float*)d_in[8];
    const float* Wo = (const float*)d_in[9];  const float* bo = (const float*)d_in[10];
    const float* bpar = (const float*)d_in[11];
    const float* epar = (const float*)d_in[12];

    __nv_bfloat16 *ah, *al, *wh, *wl, *pq, *pk, *oh, *ol;
    __half *pvh;
    cudaGetSymbolAddress((void**)&ah, g_ah);
    cudaGetSymbolAddress((void**)&al, g_al);
    cudaGetSymbolAddress((void**)&wh, g_wh);
    cudaGetSymbolAddress((void**)&wl, g_wl);
    cudaGetSymbolAddress((void**)&pq, g_q);
    cudaGetSymbolAddress((void**)&pk, g_k);
    cudaGetSymbolAddress((void**)&pvh, g_vh);
    cudaGetSymbolAddress((void**)&oh, g_oh);
    cudaGetSymbolAddress((void**)&ol, g_ol);

    const int N4  = MROWS*EMB/4;
    const int NW4 = EMB*EMB/4;
    const size_t IN = (size_t)MROWS*EMB;
    const size_t WN = (size_t)EMB*EMB;

    cudaFuncSetAttribute(gemm_fused3, cudaFuncAttributeMaxDynamicSharedMemorySize, GEMM_SMEM);
    cudaFuncSetAttribute(gemm_single, cudaFuncAttributeMaxDynamicSharedMemorySize, GEMM_SMEM);

    {
        SplitJob jw0 = { (const float4*)Wq, (uint2*)(wh + 0*WN), (uint2*)(wl + 0*WN), NW4 };
        SplitJob jw1 = { (const float4*)Wk, (uint2*)(wh + 1*WN), (uint2*)(wl + 1*WN), NW4 };
        SplitJob jw2 = { (const float4*)Wv, (uint2*)(wh + 2*WN), (uint2*)(wl + 2*WN), NW4 };
        SplitJob jw3 = { (const float4*)Wo, (uint2*)(wh + 3*WN), (uint2*)(wl + 3*WN), NW4 };
        split_multi<<<dim3(NW4/256, 4), 256>>>(jw0, jw1, jw2, jw3);
    }
    {
        SplitJob ji0 = { (const float4*)query,  (uint2*)(ah + 0*IN), (uint2*)(al + 0*IN), N4 };
        SplitJob ji1 = { (const float4*)keys,   (uint2*)(ah + 1*IN), (uint2*)(al + 1*IN), N4 };
        SplitJob ji2 = { (const float4*)values, (uint2*)(ah + 2*IN), (uint2*)(al + 2*IN), N4 };
        SplitJob ji3 = { (const float4*)query,  (uint2*)(ah + 0*IN), (uint2*)(al + 0*IN), 0 };
        split_multi<<<dim3(1024, 3), 256>>>(ji0, ji1, ji2, ji3);
    }

    // fused q/k/v projection GEMMs
    {
        GemmJob j0 = { ah + 0*IN, al + 0*IN, wh + 0*WN, wl + 0*WN, bq, pq,  1 };
        GemmJob j1 = { ah + 1*IN, al + 1*IN, wh + 1*WN, wl + 1*WN, bk, pk,  1 };
        GemmJob j2 = { ah + 2*IN, al + 2*IN, wh + 2*WN, wl + 2*WN, bv, pvh, 2 };
        gemm_fused3<<<dim3(EMB/128, MROWS/128, 3), 256, GEMM_SMEM>>>(j0, j1, j2, bpar, epar);
    }

    flash_hmma<<<dim3(SEQ/64, NHEAD, BATCH), 128>>>(pq, pk, pvh, oh, ol);

    {
        GemmJob jo = { oh, ol, wh + 3*WN, wl + 3*WN, bo, (float*)d_out, 0 };
        gemm_single<<<dim3(EMB/128, MROWS/128), 256, GEMM_SMEM>>>(jo, bpar, epar);
    }
}